// round 12
// baseline (speedup 1.0000x reference)
#include <cuda_runtime.h>
#include <math.h>

#define N1V 200000
#define BGR 8
#define NPG 25000
#define NN2 199
#define NT  (N1V + NN2)          // combined node count
#define NTP (N1V + 256)          // padded scratch rows
#define KSEL 50
#define E1MAX 2000000
#define E2MAX 4096

// ---------------- scratch (combined graphs) ----------------
__device__ __align__(16) float g_t[(size_t)NTP * 128];
__device__ __align__(16) float g_agg[(size_t)NTP * 128];
__device__ __align__(16) float g_h[(size_t)NTP * 128];
__device__ __align__(16) float g_u[(size_t)NTP * 64];
__device__ __align__(16) float g_aggu[(size_t)NTP * 64];
__device__ __align__(16) float g_o[(size_t)NTP * 64];

__device__ __align__(16) unsigned g_deg[NTP];
__device__ __align__(16) unsigned g_off[NTP];
__device__ __align__(16) unsigned g_cur[NTP];
__device__ __align__(16) int      g_csr[E1MAX + E2MAX];
__device__ __align__(16) unsigned g_bsum[256];

__device__ __align__(16) float    g_keys[N1V];
__device__ __align__(16) float    g_ref[64];
__device__ __align__(16) unsigned g_hist[BGR * 65536];
__device__ __align__(16) unsigned g_thr[BGR];
__device__ __align__(16) unsigned g_cnt[BGR];
__device__ __align__(16) int      g_cidx[BGR * NPG];
__device__ __align__(16) float    g_ckey[BGR * NPG];
__device__ __align__(16) int      g_sel[BGR * KSEL];
__device__ __align__(16) float    g_pooled[BGR * KSEL * NN2];

// packed f32x2 FMA (exact fp32 per lane)
__device__ __forceinline__ void ffma2(unsigned long long& d, unsigned long long a, unsigned long long b) {
    asm("fma.rn.f32x2 %0, %1, %2, %3;" : "=l"(d) : "l"(a), "l"(b), "l"(d));
}
__device__ __forceinline__ unsigned long long dup_f32x2(float b) {
    unsigned long long r;
    asm("mov.b64 %0, {%1, %1};" : "=l"(r) : "f"(b));
    return r;
}

// ---------------- zero ----------------
__global__ void zero4_k(float4* p, int n4) {
    int i = blockIdx.x * blockDim.x + threadIdx.x;
    if (i < n4) p[i] = make_float4(0.f, 0.f, 0.f, 0.f);
}

// ---------------- CSR build (combined, merged graphs in one launch) ----------------
__global__ void deg2_k(const int* __restrict__ d1, int E1c,
                       const int* __restrict__ d2, int E2c,
                       unsigned* __restrict__ deg) {
    int e = blockIdx.x * blockDim.x + threadIdx.x;
    if (e < E1c) atomicAdd(&deg[d1[e]], 1u);
    else if (e < E1c + E2c) atomicAdd(&deg[d2[e - E1c] + N1V], 1u);
}

__global__ void scan_block_k(const unsigned* __restrict__ in, unsigned* __restrict__ out,
                             unsigned* __restrict__ blocksum, int N) {
    __shared__ unsigned warp_tot[8];
    int t = threadIdx.x;
    int base = blockIdx.x * 1024 + t * 4;
    unsigned v0 = (base + 0 < N) ? in[base + 0] : 0u;
    unsigned v1 = (base + 1 < N) ? in[base + 1] : 0u;
    unsigned v2 = (base + 2 < N) ? in[base + 2] : 0u;
    unsigned v3 = (base + 3 < N) ? in[base + 3] : 0u;
    unsigned s = v0 + v1 + v2 + v3;
    unsigned x = s;
#pragma unroll
    for (int o = 1; o < 32; o <<= 1) {
        unsigned y = __shfl_up_sync(0xffffffffu, x, o);
        if ((t & 31) >= o) x += y;
    }
    if ((t & 31) == 31) warp_tot[t >> 5] = x;
    __syncthreads();
    if (t < 32) {
        unsigned w = (t < 8) ? warp_tot[t] : 0u;
        unsigned wx = w;
#pragma unroll
        for (int o = 1; o < 8; o <<= 1) {
            unsigned y = __shfl_up_sync(0xffffffffu, wx, o);
            if (t >= o) wx += y;
        }
        if (t == 7) blocksum[blockIdx.x] = wx;
        if (t < 8) warp_tot[t] = wx - w;
    }
    __syncthreads();
    unsigned run = warp_tot[t >> 5] + (x - s);
    if (base + 0 < N) out[base + 0] = run; run += v0;
    if (base + 1 < N) out[base + 1] = run; run += v1;
    if (base + 2 < N) out[base + 2] = run; run += v2;
    if (base + 3 < N) out[base + 3] = run;
}

__global__ void scan_top_k(unsigned* bs, int nb) {
    __shared__ unsigned wsum[8];
    int t = threadIdx.x;
    int lane = t & 31, w = t >> 5;
    unsigned v = (t < nb) ? bs[t] : 0u;
    unsigned x = v;
#pragma unroll
    for (int o = 1; o < 32; o <<= 1) {
        unsigned y = __shfl_up_sync(0xffffffffu, x, o);
        if (lane >= o) x += y;
    }
    if (lane == 31) wsum[w] = x;
    __syncthreads();
    if (t == 0) {
        unsigned run = 0;
#pragma unroll
        for (int i = 0; i < 8; i++) { unsigned tmp = wsum[i]; wsum[i] = run; run += tmp; }
    }
    __syncthreads();
    if (t < nb) bs[t] = wsum[w] + x - v;
}

// adds block prefix AND zeroes the fill-cursor array
__global__ void scan_add_k(unsigned* out, unsigned* cur, const unsigned* __restrict__ bs, int N) {
    int i = blockIdx.x * 1024 + threadIdx.x * 4;
    unsigned b = bs[blockIdx.x];
#pragma unroll
    for (int j = 0; j < 4; j++)
        if (i + j < N) { out[i + j] += b; cur[i + j] = 0u; }
}

__global__ void fill2_k(const int* __restrict__ s1, const int* __restrict__ d1, int E1c,
                        const int* __restrict__ s2, const int* __restrict__ d2, int E2c,
                        const unsigned* __restrict__ offs, unsigned* __restrict__ cur,
                        int* __restrict__ csr) {
    int e = blockIdx.x * blockDim.x + threadIdx.x;
    if (e < E1c) {
        int d = d1[e];
        unsigned p = offs[d] + atomicAdd(&cur[d], 1u);
        csr[p] = s1[e];
    } else if (e < E1c + E2c) {
        int e2 = e - E1c;
        int d = d2[e2] + N1V;
        unsigned p = offs[d] + atomicAdd(&cur[d], 1u);
        csr[p] = s2[e2] + N1V;
    }
}

// ---------------- gather aggregation with fused GIN epilogue ----------------
template<int D>
__global__ __launch_bounds__(256)
void agg_k(const float* __restrict__ V, const int* __restrict__ csr,
           const unsigned* __restrict__ off, const unsigned* __restrict__ deg,
           const float* __restrict__ bias, float* __restrict__ O, int N) {
    const int G = D / 4;
    int tid = blockIdx.x * blockDim.x + threadIdx.x;
    int node = tid / G;
    int lane = tid % G;
    if (node >= N) return;
    unsigned s0 = off[node], dn = deg[node];
    float4 accA = make_float4(0.f, 0.f, 0.f, 0.f);
    float4 accB = make_float4(0.f, 0.f, 0.f, 0.f);
    unsigned j = 0;
    for (; j + 4 <= dn; j += 4) {
        int i0 = csr[s0 + j + 0], i1 = csr[s0 + j + 1];
        int i2 = csr[s0 + j + 2], i3 = csr[s0 + j + 3];
        float4 a0 = *(const float4*)(V + (size_t)i0 * D + lane * 4);
        float4 a1 = *(const float4*)(V + (size_t)i1 * D + lane * 4);
        float4 a2 = *(const float4*)(V + (size_t)i2 * D + lane * 4);
        float4 a3 = *(const float4*)(V + (size_t)i3 * D + lane * 4);
        accA.x += a0.x + a1.x; accA.y += a0.y + a1.y;
        accA.z += a0.z + a1.z; accA.w += a0.w + a1.w;
        accB.x += a2.x + a3.x; accB.y += a2.y + a3.y;
        accB.z += a2.z + a3.z; accB.w += a2.w + a3.w;
    }
    for (; j < dn; j++) {
        int i0 = csr[s0 + j];
        float4 a0 = *(const float4*)(V + (size_t)i0 * D + lane * 4);
        accA.x += a0.x; accA.y += a0.y; accA.z += a0.z; accA.w += a0.w;
    }
    float4 self = *(const float4*)(V + (size_t)node * D + lane * 4);
    float4 b = *(const float4*)(bias + lane * 4);
    float4 o;
    o.x = fmaxf(accA.x + accB.x + self.x + b.x, 0.f);
    o.y = fmaxf(accA.y + accB.y + self.y + b.y, 0.f);
    o.z = fmaxf(accA.z + accB.z + self.z + b.z, 0.f);
    o.w = fmaxf(accA.w + accB.w + self.w + b.w, 0.f);
    *(float4*)(O + (size_t)node * D + lane * 4) = o;
}

// ---------------- hist zero + reference row (merged) ----------------
// all blocks zero hist; last block additionally computes
// ref = relu(aggu[N1V+198] @ W2b + b2b) in threads < 64.
__global__ void prep_sel_k(float4* __restrict__ hist4, int n4,
                           const float* __restrict__ aggu, const float* __restrict__ W2b,
                           const float* __restrict__ b2b, float* __restrict__ ref) {
    int i = blockIdx.x * blockDim.x + threadIdx.x;
    if (i < n4) hist4[i] = make_float4(0.f, 0.f, 0.f, 0.f);
    if (blockIdx.x == gridDim.x - 1 && threadIdx.x < 64) {
        int c = threadIdx.x;
        const float* a = aggu + (size_t)(N1V + 198) * 64;
        float s = b2b[c];
        for (int k = 0; k < 64; k++) s = fmaf(a[k], W2b[k * 64 + c], s);
        ref[c] = fmaxf(s, 0.f);
    }
}

// ---------------- SGEMM (FFMA2, frozen): C = A @ W (+bout)(+relu) ----------------
// KEYS: fused per-row squared-distance-to-ref + histogram (final gemm only).
template<bool RELU_OUT, bool KEYS>
__global__ __launch_bounds__(256)
void gemm_k(const float* __restrict__ A1, const float* __restrict__ A2, int N1,
            const float* __restrict__ W, const float* __restrict__ bout,
            float* __restrict__ C, int N, int K, int Co,
            const float* __restrict__ refp, float* __restrict__ keys,
            unsigned* __restrict__ hist)
{
    const int BM = 128, BN = 64, BK = 16;
    __shared__ float As[BK][BM + 4];
    __shared__ float Bs[BK][BN + 4];

    int tid = threadIdx.x;
    int rowBase = blockIdx.y * BM;
    int colBase = blockIdx.x * BN;
    int tx = tid & 15;
    int ty = tid >> 4;

    unsigned long long acc2[4][4];
#pragma unroll
    for (int p = 0; p < 4; p++)
#pragma unroll
        for (int j = 0; j < 4; j++) acc2[p][j] = 0ull;

    for (int k0 = 0; k0 < K; k0 += BK) {
        {
            int row = tid >> 1;
            int kk = (tid & 1) * 8;
            int r = rowBase + row;
            if (r < N) {
                const float* pA = (r < N1) ? (A1 + (size_t)r * K)
                                           : (A2 + (size_t)(r - N1) * K);
                pA += k0 + kk;
                float4 v0 = *(const float4*)(pA);
                float4 v1 = *(const float4*)(pA + 4);
                As[kk + 0][row] = v0.x; As[kk + 1][row] = v0.y;
                As[kk + 2][row] = v0.z; As[kk + 3][row] = v0.w;
                As[kk + 4][row] = v1.x; As[kk + 5][row] = v1.y;
                As[kk + 6][row] = v1.z; As[kk + 7][row] = v1.w;
            } else {
#pragma unroll
                for (int i = 0; i < 8; i++) As[kk + i][row] = 0.f;
            }
        }
        {
            int k = tid >> 4;
            int c = (tid & 15) * 4;
            float4 v = *(const float4*)(W + (size_t)(k0 + k) * Co + colBase + c);
            Bs[k][c + 0] = v.x; Bs[k][c + 1] = v.y;
            Bs[k][c + 2] = v.z; Bs[k][c + 3] = v.w;
        }
        __syncthreads();

#pragma unroll
        for (int k = 0; k < BK; k++) {
            const unsigned long long* a2p =
                (const unsigned long long*)&As[k][ty * 8];
            unsigned long long a2[4];
#pragma unroll
            for (int p = 0; p < 4; p++) a2[p] = a2p[p];
            unsigned long long bb[4];
#pragma unroll
            for (int j = 0; j < 4; j++) bb[j] = dup_f32x2(Bs[k][tx * 4 + j]);
#pragma unroll
            for (int p = 0; p < 4; p++)
#pragma unroll
                for (int j = 0; j < 4; j++) ffma2(acc2[p][j], a2[p], bb[j]);
        }
        __syncthreads();
    }

    float rf[4];
    if (KEYS) {
#pragma unroll
        for (int j = 0; j < 4; j++) rf[j] = refp[tx * 4 + j];
    }

#pragma unroll
    for (int p = 0; p < 4; p++) {
#pragma unroll
        for (int half = 0; half < 2; half++) {
            int r = rowBase + ty * 8 + 2 * p + half;
            float4 v;
            float tmp[4];
#pragma unroll
            for (int j = 0; j < 4; j++) {
                float lo, hi;
                asm("mov.b64 {%0, %1}, %2;" : "=f"(lo), "=f"(hi) : "l"(acc2[p][j]));
                tmp[j] = half ? hi : lo;
            }
            v.x = tmp[0]; v.y = tmp[1]; v.z = tmp[2]; v.w = tmp[3];
            int c = colBase + tx * 4;
            if (bout) {
                v.x += bout[c + 0]; v.y += bout[c + 1];
                v.z += bout[c + 2]; v.w += bout[c + 3];
            }
            if (RELU_OUT) {
                v.x = fmaxf(v.x, 0.f); v.y = fmaxf(v.y, 0.f);
                v.z = fmaxf(v.z, 0.f); v.w = fmaxf(v.w, 0.f);
            }
            if (r < N)
                *(float4*)(C + (size_t)r * Co + c) = v;

            if (KEYS) {
                float d0 = v.x - rf[0], d1 = v.y - rf[1];
                float d2 = v.z - rf[2], d3 = v.w - rf[3];
                float kp = d0 * d0 + d1 * d1 + d2 * d2 + d3 * d3;
                kp += __shfl_xor_sync(0xffffffffu, kp, 1);
                kp += __shfl_xor_sync(0xffffffffu, kp, 2);
                kp += __shfl_xor_sync(0xffffffffu, kp, 4);
                kp += __shfl_xor_sync(0xffffffffu, kp, 8);
                if (tx == 0 && r < N1V) {
                    keys[r] = kp;
                    unsigned b = __float_as_uint(kp) >> 16;
                    atomicAdd(&hist[(r / NPG) * 65536 + b], 1u);
                }
            }
        }
    }
}

// also zeroes cnt[g]
__global__ void thresh_k(const unsigned* __restrict__ hist, unsigned* __restrict__ thr,
                         unsigned* __restrict__ cnt)
{
    int g = blockIdx.x;
    int t = threadIdx.x;
    __shared__ unsigned csum[256];
    const unsigned* h = hist + g * 65536;
    unsigned s = 0;
    for (int b = 0; b < 256; b++) s += h[t * 256 + b];
    csum[t] = s;
    __syncthreads();
    if (t == 0) {
        cnt[g] = 0u;
        unsigned cum = 0;
        int chunk = 255;
        for (; chunk >= 0; chunk--) {
            if (cum + csum[chunk] >= KSEL) break;
            cum += csum[chunk];
        }
        unsigned c2 = cum;
        int b = chunk * 256 + 255;
        for (; b >= chunk * 256; b--) {
            c2 += h[b];
            if (c2 >= KSEL) break;
        }
        thr[g] = (unsigned)b;
    }
}

__global__ void collect_k(const float* __restrict__ keys, const unsigned* __restrict__ thr,
                          unsigned* __restrict__ cnt, int* __restrict__ cidx,
                          float* __restrict__ ckey)
{
    int i = blockIdx.x * blockDim.x + threadIdx.x;
    if (i >= N1V) return;
    int g = i / NPG;
    float k = keys[i];
    if ((__float_as_uint(k) >> 16) >= thr[g]) {
        unsigned p = atomicAdd(&cnt[g], 1u);
        cidx[g * NPG + p] = i;
        ckey[g * NPG + p] = k;
    }
}

__global__ void select_k(const unsigned* __restrict__ cnt, const int* __restrict__ cidx,
                         const float* __restrict__ ckey, int* __restrict__ sel)
{
    int g = blockIdx.x;
    int M = (int)cnt[g];
    const int* idx = cidx + g * NPG;
    const float* key = ckey + g * NPG;
    for (int c = threadIdx.x; c < M; c += blockDim.x) {
        float kc = key[c];
        int ic = idx[c];
        int rank = 0;
        for (int j = 0; j < M; j++) {
            float kj = key[j];
            if (kj > kc || (kj == kc && idx[j] < ic)) rank++;
        }
        if (rank < KSEL) sel[g * KSEL + rank] = ic;
    }
}

__global__ void pool_k(const float* __restrict__ o1, const float* __restrict__ o2,
                       const int* __restrict__ sel, float* __restrict__ pooled)
{
    __shared__ float a[64];
    int gr = blockIdx.x;
    int node = sel[gr];
    int t = threadIdx.x;
    if (t < 64) a[t] = o1[(size_t)node * 64 + t];
    __syncthreads();
    if (t < NN2) {
        const float* b = o2 + t * 64;
        float s = 0.f;
#pragma unroll
        for (int c = 0; c < 64; c++) {
            float d = a[c] - b[c];
            s += d * d;
        }
        pooled[gr * NN2 + t] = sqrtf(s);
    }
}

// head: 256 threads. fc1 split 2-way over k with 4 independent partials
// (breaks the 9950-long serial FMA chain); LN/fc2/fc3 on threads < 128.
__global__ void head_k(const float* __restrict__ pooled,
                       const float* __restrict__ fc1W, const float* __restrict__ fc1b,
                       const float* __restrict__ g1, const float* __restrict__ be1,
                       const float* __restrict__ fc2W, const float* __restrict__ fc2b,
                       const float* __restrict__ g2, const float* __restrict__ be2,
                       const float* __restrict__ fc3W, const float* __restrict__ fc3b,
                       float* __restrict__ out)
{
    int g = blockIdx.x;
    int t = threadIdx.x;          // 256
    int col = t & 127;
    int half = t >> 7;
    __shared__ float part[256];
    __shared__ float sh[128];
    __shared__ float red[128];
    const float* p = pooled + g * (KSEL * NN2);

    const int KT = KSEL * NN2;            // 9950
    const int KH = KT / 2;                // 4975
    int k0 = half * KH, k1 = k0 + KH;
    float s0 = 0.f, s1 = 0.f, s2 = 0.f, s3 = 0.f;
    int k = k0;
    for (; k + 4 <= k1; k += 4) {
        s0 = fmaf(p[k + 0], fc1W[(size_t)(k + 0) * 128 + col], s0);
        s1 = fmaf(p[k + 1], fc1W[(size_t)(k + 1) * 128 + col], s1);
        s2 = fmaf(p[k + 2], fc1W[(size_t)(k + 2) * 128 + col], s2);
        s3 = fmaf(p[k + 3], fc1W[(size_t)(k + 3) * 128 + col], s3);
    }
    for (; k < k1; k++) s0 = fmaf(p[k], fc1W[(size_t)k * 128 + col], s0);
    part[t] = ((s0 + s1) + (s2 + s3));
    __syncthreads();

    float s = 0.f;
    if (t < 128) s = part[t] + part[t + 128] + fc1b[t];

    // LayerNorm over 128 (threads >= 128 idle but hit barriers)
    if (t < 128) red[t] = s;
    __syncthreads();
    for (int o = 64; o > 0; o >>= 1) { if (t < o) red[t] += red[t + o]; __syncthreads(); }
    float mu = red[0] / 128.f; __syncthreads();
    float d = (t < 128) ? (s - mu) : 0.f;
    if (t < 128) red[t] = d * d;
    __syncthreads();
    for (int o = 64; o > 0; o >>= 1) { if (t < o) red[t] += red[t + o]; __syncthreads(); }
    float var = red[0] / 128.f; __syncthreads();
    if (t < 128) sh[t] = fmaxf(d * rsqrtf(var + 1e-5f) * g1[t] + be1[t], 0.f);
    __syncthreads();

    float s2b = 0.f;
    if (t < 64) {
        s2b = fc2b[t];
        float a0 = 0.f, a1 = 0.f;
        for (int kk = 0; kk < 128; kk += 2) {
            a0 = fmaf(sh[kk], fc2W[kk * 64 + t], a0);
            a1 = fmaf(sh[kk + 1], fc2W[(kk + 1) * 64 + t], a1);
        }
        s2b += a0 + a1;
    }
    __syncthreads();
    if (t < 128) red[t] = (t < 64) ? s2b : 0.f;
    __syncthreads();
    for (int o = 64; o > 0; o >>= 1) { if (t < o) red[t] += red[t + o]; __syncthreads(); }
    float mu2 = red[0] / 64.f; __syncthreads();
    float d2 = (t < 64) ? (s2b - mu2) : 0.f;
    if (t < 128) red[t] = d2 * d2;
    __syncthreads();
    for (int o = 64; o > 0; o >>= 1) { if (t < o) red[t] += red[t + o]; __syncthreads(); }
    float var2 = red[0] / 64.f; __syncthreads();
    if (t < 64) sh[t] = fmaxf(d2 * rsqrtf(var2 + 1e-5f) * g2[t] + be2[t], 0.f);
    __syncthreads();

    if (t == 0) {
        float o = fc3b[0];
        for (int kk = 0; kk < 64; kk++) o = fmaf(sh[kk], fc3W[kk], o);
        out[g] = 1.f / (1.f + expf(-o));
    }
}

// ---------------- launch ----------------
extern "C" void kernel_launch(void* const* d_in, const int* in_sizes, int n_in,
                              void* d_out, int out_size)
{
    const float* x1 = (const float*)d_in[0];
    const int* ei1 = (const int*)d_in[1];
    const float* x2 = (const float*)d_in[3];
    const int* ei2 = (const int*)d_in[4];
    const float* W1a = (const float*)d_in[5];  const float* b1a = (const float*)d_in[6];
    const float* W1b = (const float*)d_in[7];  const float* b1b = (const float*)d_in[8];
    const float* W2a = (const float*)d_in[9];  const float* b2a = (const float*)d_in[10];
    const float* W2b = (const float*)d_in[11]; const float* b2b = (const float*)d_in[12];
    const float* fc1W = (const float*)d_in[13]; const float* fc1b = (const float*)d_in[14];
    const float* g1 = (const float*)d_in[15];   const float* be1 = (const float*)d_in[16];
    const float* fc2W = (const float*)d_in[17]; const float* fc2b = (const float*)d_in[18];
    const float* g2 = (const float*)d_in[19];   const float* be2 = (const float*)d_in[20];
    const float* fc3W = (const float*)d_in[21]; const float* fc3b = (const float*)d_in[22];
    float* out = (float*)d_out;

    int E1 = in_sizes[1] / 2;
    int E2 = in_sizes[4] / 2;

    float *t, *agg, *h, *u, *aggu, *o;
    float *keys, *ckey, *pooled, *refp;
    unsigned *hist, *thr, *cnt;
    int *cidx, *sel;
    unsigned *deg, *off, *cur, *bsum;
    int *csr;
    cudaGetSymbolAddress((void**)&t, g_t);
    cudaGetSymbolAddress((void**)&agg, g_agg);
    cudaGetSymbolAddress((void**)&h, g_h);
    cudaGetSymbolAddress((void**)&u, g_u);
    cudaGetSymbolAddress((void**)&aggu, g_aggu);
    cudaGetSymbolAddress((void**)&o, g_o);
    cudaGetSymbolAddress((void**)&keys, g_keys);
    cudaGetSymbolAddress((void**)&refp, g_ref);
    cudaGetSymbolAddress((void**)&hist, g_hist);
    cudaGetSymbolAddress((void**)&thr, g_thr);
    cudaGetSymbolAddress((void**)&cnt, g_cnt);
    cudaGetSymbolAddress((void**)&cidx, g_cidx);
    cudaGetSymbolAddress((void**)&ckey, g_ckey);
    cudaGetSymbolAddress((void**)&sel, g_sel);
    cudaGetSymbolAddress((void**)&pooled, g_pooled);
    cudaGetSymbolAddress((void**)&deg, g_deg);
    cudaGetSymbolAddress((void**)&off, g_off);
    cudaGetSymbolAddress((void**)&cur, g_cur);
    cudaGetSymbolAddress((void**)&csr, g_csr);
    cudaGetSymbolAddress((void**)&bsum, g_bsum);

    const float* o2p = o + (size_t)N1V * 64;   // graph2 output rows

    int gy = (NT + 127) / 128;                 // 1565
    int nb = (NT + 1023) / 1024;               // 196
    int Etot = E1 + E2;

    // ===== combined CSR build (6 launches) =====
    zero4_k<<<(NTP / 4 + 255) / 256, 256>>>((float4*)deg, NTP / 4);
    deg2_k<<<(Etot + 255) / 256, 256>>>(ei1 + E1, E1, ei2 + E2, E2, deg);
    scan_block_k<<<nb, 256>>>(deg, off, bsum, NT);
    scan_top_k<<<1, 256>>>(bsum, nb);
    scan_add_k<<<nb, 256>>>(off, cur, bsum, NT);
    fill2_k<<<(Etot + 255) / 256, 256>>>(ei1, ei1 + E1, E1, ei2, ei2 + E2, E2, off, cur, csr);

    // ===== combined GIN (7 launches incl. prep) =====
    gemm_k<false, false><<<dim3(2, gy), 256>>>(x1, x2, N1V, W1a, nullptr, t, NT, 128, 128,
                                               nullptr, nullptr, nullptr);
    agg_k<128><<<(NT * 32 + 255) / 256, 256>>>(t, csr, off, deg, b1a, agg, NT);
    gemm_k<true, false><<<dim3(2, gy), 256>>>(agg, agg, NT + 256, W1b, b1b, h, NT, 128, 128,
                                              nullptr, nullptr, nullptr);

    gemm_k<false, false><<<dim3(1, gy), 256>>>(h, h, NT + 256, W2a, nullptr, u, NT, 128, 64,
                                               nullptr, nullptr, nullptr);
    agg_k<64><<<(NT * 16 + 255) / 256, 256>>>(u, csr, off, deg, b2a, aggu, NT);

    prep_sel_k<<<(BGR * 65536 / 4 + 255) / 256, 256>>>((float4*)hist, BGR * 65536 / 4,
                                                       aggu, W2b, b2b, refp);
    gemm_k<true, true><<<dim3(1, gy), 256>>>(aggu, aggu, NT + 256, W2b, b2b, o, NT, 64, 64,
                                             refp, keys, hist);

    // ===== selection (3 launches) =====
    thresh_k<<<BGR, 256>>>(hist, thr, cnt);
    collect_k<<<(N1V + 255) / 256, 256>>>(keys, thr, cnt, cidx, ckey);
    select_k<<<BGR, 256>>>(cnt, cidx, ckey, sel);

    // ===== pooled distances + head (2 launches) =====
    pool_k<<<BGR * KSEL, 256>>>(o, o2p, sel, pooled);
    head_k<<<BGR, 256>>>(pooled, fc1W, fc1b, g1, be1, fc2W, fc2b, g2, be2, fc3W, fc3b, out);
}

// round 13
// speedup vs baseline: 1.3304x; 1.3304x over previous
#include <cuda_runtime.h>
#include <math.h>

#define N1V 200000
#define BGR 8
#define NPG 25000
#define NN2 199
#define NT  (N1V + NN2)          // combined node count
#define NTP (N1V + 256)          // padded scratch rows
#define KSEL 50
#define E1MAX 2000000
#define E2MAX 4096

// ---------------- scratch (combined graphs) ----------------
__device__ __align__(16) float g_t[(size_t)NTP * 128];
__device__ __align__(16) float g_agg[(size_t)NTP * 128];
__device__ __align__(16) float g_h[(size_t)NTP * 128];
__device__ __align__(16) float g_u[(size_t)NTP * 64];
__device__ __align__(16) float g_aggu[(size_t)NTP * 64];
__device__ __align__(16) float g_o[(size_t)NTP * 64];

__device__ __align__(16) unsigned g_deg[NTP];
__device__ __align__(16) unsigned g_off[NTP];
__device__ __align__(16) unsigned g_cur[NTP];
__device__ __align__(16) int      g_csr[E1MAX + E2MAX];
__device__ __align__(16) unsigned g_bsum[256];

__device__ __align__(16) float    g_keys[N1V];
__device__ __align__(16) float    g_ref[64];
__device__ __align__(16) unsigned g_hist[BGR * 65536];
__device__ __align__(16) unsigned g_thr[BGR];
__device__ __align__(16) unsigned g_cnt[BGR];
__device__ __align__(16) int      g_cidx[BGR * NPG];
__device__ __align__(16) float    g_ckey[BGR * NPG];
__device__ __align__(16) int      g_sel[BGR * KSEL];
__device__ __align__(16) float    g_pooled[BGR * KSEL * NN2];

// packed f32x2 FMA (exact fp32 per lane)
__device__ __forceinline__ void ffma2(unsigned long long& d, unsigned long long a, unsigned long long b) {
    asm("fma.rn.f32x2 %0, %1, %2, %3;" : "=l"(d) : "l"(a), "l"(b), "l"(d));
}
__device__ __forceinline__ unsigned long long dup_f32x2(float b) {
    unsigned long long r;
    asm("mov.b64 %0, {%1, %1};" : "=l"(r) : "f"(b));
    return r;
}

// ---------------- zero ----------------
__global__ void zero4_k(float4* p, int n4) {
    int i = blockIdx.x * blockDim.x + threadIdx.x;
    if (i < n4) p[i] = make_float4(0.f, 0.f, 0.f, 0.f);
}

// ---------------- CSR build (combined) ----------------
__global__ void deg_k(const int* __restrict__ dst, int E, int off,
                      unsigned* __restrict__ deg) {
    int e = blockIdx.x * blockDim.x + threadIdx.x;
    if (e < E) atomicAdd(&deg[dst[e] + off], 1u);
}

__global__ void scan_block_k(const unsigned* __restrict__ in, unsigned* __restrict__ out,
                             unsigned* __restrict__ blocksum, int N) {
    __shared__ unsigned warp_tot[8];
    int t = threadIdx.x;
    int base = blockIdx.x * 1024 + t * 4;
    unsigned v0 = (base + 0 < N) ? in[base + 0] : 0u;
    unsigned v1 = (base + 1 < N) ? in[base + 1] : 0u;
    unsigned v2 = (base + 2 < N) ? in[base + 2] : 0u;
    unsigned v3 = (base + 3 < N) ? in[base + 3] : 0u;
    unsigned s = v0 + v1 + v2 + v3;
    unsigned x = s;
#pragma unroll
    for (int o = 1; o < 32; o <<= 1) {
        unsigned y = __shfl_up_sync(0xffffffffu, x, o);
        if ((t & 31) >= o) x += y;
    }
    if ((t & 31) == 31) warp_tot[t >> 5] = x;
    __syncthreads();
    if (t < 32) {
        unsigned w = (t < 8) ? warp_tot[t] : 0u;
        unsigned wx = w;
#pragma unroll
        for (int o = 1; o < 8; o <<= 1) {
            unsigned y = __shfl_up_sync(0xffffffffu, wx, o);
            if (t >= o) wx += y;
        }
        if (t == 7) blocksum[blockIdx.x] = wx;
        if (t < 8) warp_tot[t] = wx - w;
    }
    __syncthreads();
    unsigned run = warp_tot[t >> 5] + (x - s);
    if (base + 0 < N) out[base + 0] = run; run += v0;
    if (base + 1 < N) out[base + 1] = run; run += v1;
    if (base + 2 < N) out[base + 2] = run; run += v2;
    if (base + 3 < N) out[base + 3] = run;
}

__global__ void scan_top_k(unsigned* bs, int nb) {
    __shared__ unsigned wsum[8];
    int t = threadIdx.x;
    int lane = t & 31, w = t >> 5;
    unsigned v = (t < nb) ? bs[t] : 0u;
    unsigned x = v;
#pragma unroll
    for (int o = 1; o < 32; o <<= 1) {
        unsigned y = __shfl_up_sync(0xffffffffu, x, o);
        if (lane >= o) x += y;
    }
    if (lane == 31) wsum[w] = x;
    __syncthreads();
    if (t == 0) {
        unsigned run = 0;
#pragma unroll
        for (int i = 0; i < 8; i++) { unsigned tmp = wsum[i]; wsum[i] = run; run += tmp; }
    }
    __syncthreads();
    if (t < nb) bs[t] = wsum[w] + x - v;
}

// adds block prefix AND zeroes the fill-cursor array
__global__ void scan_add_k(unsigned* out, unsigned* cur, const unsigned* __restrict__ bs, int N) {
    int i = blockIdx.x * 1024 + threadIdx.x * 4;
    unsigned b = bs[blockIdx.x];
#pragma unroll
    for (int j = 0; j < 4; j++)
        if (i + j < N) { out[i + j] += b; cur[i + j] = 0u; }
}

__global__ void fill_k(const int* __restrict__ src, const int* __restrict__ dst, int E, int off,
                       const unsigned* __restrict__ offs, unsigned* __restrict__ cur,
                       int* __restrict__ csr) {
    int e = blockIdx.x * blockDim.x + threadIdx.x;
    if (e < E) {
        int d = dst[e] + off;
        unsigned p = offs[d] + atomicAdd(&cur[d], 1u);
        csr[p] = src[e] + off;
    }
}

// ---------------- gather aggregation with fused GIN epilogue ----------------
template<int D>
__global__ __launch_bounds__(256)
void agg_k(const float* __restrict__ V, const int* __restrict__ csr,
           const unsigned* __restrict__ off, const unsigned* __restrict__ deg,
           const float* __restrict__ bias, float* __restrict__ O, int N) {
    const int G = D / 4;
    int tid = blockIdx.x * blockDim.x + threadIdx.x;
    int node = tid / G;
    int lane = tid % G;
    if (node >= N) return;
    unsigned s0 = off[node], dn = deg[node];
    float4 accA = make_float4(0.f, 0.f, 0.f, 0.f);
    float4 accB = make_float4(0.f, 0.f, 0.f, 0.f);
    unsigned j = 0;
    for (; j + 4 <= dn; j += 4) {
        int i0 = csr[s0 + j + 0], i1 = csr[s0 + j + 1];
        int i2 = csr[s0 + j + 2], i3 = csr[s0 + j + 3];
        float4 a0 = *(const float4*)(V + (size_t)i0 * D + lane * 4);
        float4 a1 = *(const float4*)(V + (size_t)i1 * D + lane * 4);
        float4 a2 = *(const float4*)(V + (size_t)i2 * D + lane * 4);
        float4 a3 = *(const float4*)(V + (size_t)i3 * D + lane * 4);
        accA.x += a0.x + a1.x; accA.y += a0.y + a1.y;
        accA.z += a0.z + a1.z; accA.w += a0.w + a1.w;
        accB.x += a2.x + a3.x; accB.y += a2.y + a3.y;
        accB.z += a2.z + a3.z; accB.w += a2.w + a3.w;
    }
    for (; j < dn; j++) {
        int i0 = csr[s0 + j];
        float4 a0 = *(const float4*)(V + (size_t)i0 * D + lane * 4);
        accA.x += a0.x; accA.y += a0.y; accA.z += a0.z; accA.w += a0.w;
    }
    float4 self = *(const float4*)(V + (size_t)node * D + lane * 4);
    float4 b = *(const float4*)(bias + lane * 4);
    float4 o;
    o.x = fmaxf(accA.x + accB.x + self.x + b.x, 0.f);
    o.y = fmaxf(accA.y + accB.y + self.y + b.y, 0.f);
    o.z = fmaxf(accA.z + accB.z + self.z + b.z, 0.f);
    o.w = fmaxf(accA.w + accB.w + self.w + b.w, 0.f);
    *(float4*)(O + (size_t)node * D + lane * 4) = o;
}

// ---------------- reference row for keys: ref = relu(aggu[N1V+198] @ W2b + b2b) ----------------
__global__ void ref_k(const float* __restrict__ aggu, const float* __restrict__ W2b,
                      const float* __restrict__ b2b, float* __restrict__ ref) {
    int c = threadIdx.x;  // 64
    const float* a = aggu + (size_t)(N1V + 198) * 64;
    float s = b2b[c];
    for (int k = 0; k < 64; k++) s = fmaf(a[k], W2b[k * 64 + c], s);
    ref[c] = fmaxf(s, 0.f);
}

// ---------------- SGEMM (FFMA2, frozen): C = A @ W (+bout)(+relu) ----------------
// KEYS: fused per-row squared-distance-to-ref + histogram (final gemm only).
template<bool RELU_OUT, bool KEYS>
__global__ __launch_bounds__(256)
void gemm_k(const float* __restrict__ A1, const float* __restrict__ A2, int N1,
            const float* __restrict__ W, const float* __restrict__ bout,
            float* __restrict__ C, int N, int K, int Co,
            const float* __restrict__ refp, float* __restrict__ keys,
            unsigned* __restrict__ hist)
{
    const int BM = 128, BN = 64, BK = 16;
    __shared__ float As[BK][BM + 4];
    __shared__ float Bs[BK][BN + 4];

    int tid = threadIdx.x;
    int rowBase = blockIdx.y * BM;
    int colBase = blockIdx.x * BN;
    int tx = tid & 15;
    int ty = tid >> 4;

    unsigned long long acc2[4][4];
#pragma unroll
    for (int p = 0; p < 4; p++)
#pragma unroll
        for (int j = 0; j < 4; j++) acc2[p][j] = 0ull;

    for (int k0 = 0; k0 < K; k0 += BK) {
        {
            int row = tid >> 1;
            int kk = (tid & 1) * 8;
            int r = rowBase + row;
            if (r < N) {
                const float* pA = (r < N1) ? (A1 + (size_t)r * K)
                                           : (A2 + (size_t)(r - N1) * K);
                pA += k0 + kk;
                float4 v0 = *(const float4*)(pA);
                float4 v1 = *(const float4*)(pA + 4);
                As[kk + 0][row] = v0.x; As[kk + 1][row] = v0.y;
                As[kk + 2][row] = v0.z; As[kk + 3][row] = v0.w;
                As[kk + 4][row] = v1.x; As[kk + 5][row] = v1.y;
                As[kk + 6][row] = v1.z; As[kk + 7][row] = v1.w;
            } else {
#pragma unroll
                for (int i = 0; i < 8; i++) As[kk + i][row] = 0.f;
            }
        }
        {
            int k = tid >> 4;
            int c = (tid & 15) * 4;
            float4 v = *(const float4*)(W + (size_t)(k0 + k) * Co + colBase + c);
            Bs[k][c + 0] = v.x; Bs[k][c + 1] = v.y;
            Bs[k][c + 2] = v.z; Bs[k][c + 3] = v.w;
        }
        __syncthreads();

#pragma unroll
        for (int k = 0; k < BK; k++) {
            const unsigned long long* a2p =
                (const unsigned long long*)&As[k][ty * 8];
            unsigned long long a2[4];
#pragma unroll
            for (int p = 0; p < 4; p++) a2[p] = a2p[p];
            unsigned long long bb[4];
#pragma unroll
            for (int j = 0; j < 4; j++) bb[j] = dup_f32x2(Bs[k][tx * 4 + j]);
#pragma unroll
            for (int p = 0; p < 4; p++)
#pragma unroll
                for (int j = 0; j < 4; j++) ffma2(acc2[p][j], a2[p], bb[j]);
        }
        __syncthreads();
    }

    float rf[4];
    if (KEYS) {
#pragma unroll
        for (int j = 0; j < 4; j++) rf[j] = refp[tx * 4 + j];
    }

#pragma unroll
    for (int p = 0; p < 4; p++) {
#pragma unroll
        for (int half = 0; half < 2; half++) {
            int r = rowBase + ty * 8 + 2 * p + half;
            float4 v;
            float tmp[4];
#pragma unroll
            for (int j = 0; j < 4; j++) {
                float lo, hi;
                asm("mov.b64 {%0, %1}, %2;" : "=f"(lo), "=f"(hi) : "l"(acc2[p][j]));
                tmp[j] = half ? hi : lo;
            }
            v.x = tmp[0]; v.y = tmp[1]; v.z = tmp[2]; v.w = tmp[3];
            int c = colBase + tx * 4;
            if (bout) {
                v.x += bout[c + 0]; v.y += bout[c + 1];
                v.z += bout[c + 2]; v.w += bout[c + 3];
            }
            if (RELU_OUT) {
                v.x = fmaxf(v.x, 0.f); v.y = fmaxf(v.y, 0.f);
                v.z = fmaxf(v.z, 0.f); v.w = fmaxf(v.w, 0.f);
            }
            if (r < N)
                *(float4*)(C + (size_t)r * Co + c) = v;

            if (KEYS) {
                float d0 = v.x - rf[0], d1 = v.y - rf[1];
                float d2 = v.z - rf[2], d3 = v.w - rf[3];
                float kp = d0 * d0 + d1 * d1 + d2 * d2 + d3 * d3;
                kp += __shfl_xor_sync(0xffffffffu, kp, 1);
                kp += __shfl_xor_sync(0xffffffffu, kp, 2);
                kp += __shfl_xor_sync(0xffffffffu, kp, 4);
                kp += __shfl_xor_sync(0xffffffffu, kp, 8);
                if (tx == 0 && r < N1V) {
                    keys[r] = kp;
                    unsigned b = __float_as_uint(kp) >> 16;
                    atomicAdd(&hist[(r / NPG) * 65536 + b], 1u);
                }
            }
        }
    }
}

// also zeroes cnt[g]
__global__ void thresh_k(const unsigned* __restrict__ hist, unsigned* __restrict__ thr,
                         unsigned* __restrict__ cnt)
{
    int g = blockIdx.x;
    int t = threadIdx.x;
    __shared__ unsigned csum[256];
    const unsigned* h = hist + g * 65536;
    unsigned s = 0;
    for (int b = 0; b < 256; b++) s += h[t * 256 + b];
    csum[t] = s;
    __syncthreads();
    if (t == 0) {
        cnt[g] = 0u;
        unsigned cum = 0;
        int chunk = 255;
        for (; chunk >= 0; chunk--) {
            if (cum + csum[chunk] >= KSEL) break;
            cum += csum[chunk];
        }
        unsigned c2 = cum;
        int b = chunk * 256 + 255;
        for (; b >= chunk * 256; b--) {
            c2 += h[b];
            if (c2 >= KSEL) break;
        }
        thr[g] = (unsigned)b;
    }
}

__global__ void collect_k(const float* __restrict__ keys, const unsigned* __restrict__ thr,
                          unsigned* __restrict__ cnt, int* __restrict__ cidx,
                          float* __restrict__ ckey)
{
    int i = blockIdx.x * blockDim.x + threadIdx.x;
    if (i >= N1V) return;
    int g = i / NPG;
    float k = keys[i];
    if ((__float_as_uint(k) >> 16) >= thr[g]) {
        unsigned p = atomicAdd(&cnt[g], 1u);
        cidx[g * NPG + p] = i;
        ckey[g * NPG + p] = k;
    }
}

__global__ void select_k(const unsigned* __restrict__ cnt, const int* __restrict__ cidx,
                         const float* __restrict__ ckey, int* __restrict__ sel)
{
    int g = blockIdx.x;
    int M = (int)cnt[g];
    const int* idx = cidx + g * NPG;
    const float* key = ckey + g * NPG;
    for (int c = threadIdx.x; c < M; c += blockDim.x) {
        float kc = key[c];
        int ic = idx[c];
        int rank = 0;
        for (int j = 0; j < M; j++) {
            float kj = key[j];
            if (kj > kc || (kj == kc && idx[j] < ic)) rank++;
        }
        if (rank < KSEL) sel[g * KSEL + rank] = ic;
    }
}

__global__ void pool_k(const float* __restrict__ o1, const float* __restrict__ o2,
                       const int* __restrict__ sel, float* __restrict__ pooled)
{
    __shared__ float a[64];
    int gr = blockIdx.x;
    int node = sel[gr];
    int t = threadIdx.x;
    if (t < 64) a[t] = o1[(size_t)node * 64 + t];
    __syncthreads();
    if (t < NN2) {
        const float* b = o2 + t * 64;
        float s = 0.f;
#pragma unroll
        for (int c = 0; c < 64; c++) {
            float d = a[c] - b[c];
            s += d * d;
        }
        pooled[gr * NN2 + t] = sqrtf(s);
    }
}

// head: 256 threads. fc1 split 2-way over k with 4 independent partials
// (breaks the 9950-long serial FMA chain); LN/fc2/fc3 on threads < 128.
__global__ void head_k(const float* __restrict__ pooled,
                       const float* __restrict__ fc1W, const float* __restrict__ fc1b,
                       const float* __restrict__ g1, const float* __restrict__ be1,
                       const float* __restrict__ fc2W, const float* __restrict__ fc2b,
                       const float* __restrict__ g2, const float* __restrict__ be2,
                       const float* __restrict__ fc3W, const float* __restrict__ fc3b,
                       float* __restrict__ out)
{
    int g = blockIdx.x;
    int t = threadIdx.x;          // 256
    int col = t & 127;
    int half = t >> 7;
    __shared__ float part[256];
    __shared__ float sh[128];
    __shared__ float red[128];
    const float* p = pooled + g * (KSEL * NN2);

    const int KT = KSEL * NN2;            // 9950
    const int KH = KT / 2;                // 4975
    int k0 = half * KH, k1 = k0 + KH;
    float s0 = 0.f, s1 = 0.f, s2 = 0.f, s3 = 0.f;
    int k = k0;
    for (; k + 4 <= k1; k += 4) {
        s0 = fmaf(p[k + 0], fc1W[(size_t)(k + 0) * 128 + col], s0);
        s1 = fmaf(p[k + 1], fc1W[(size_t)(k + 1) * 128 + col], s1);
        s2 = fmaf(p[k + 2], fc1W[(size_t)(k + 2) * 128 + col], s2);
        s3 = fmaf(p[k + 3], fc1W[(size_t)(k + 3) * 128 + col], s3);
    }
    for (; k < k1; k++) s0 = fmaf(p[k], fc1W[(size_t)k * 128 + col], s0);
    part[t] = ((s0 + s1) + (s2 + s3));
    __syncthreads();

    float s = 0.f;
    if (t < 128) s = part[t] + part[t + 128] + fc1b[t];

    if (t < 128) red[t] = s;
    __syncthreads();
    for (int o = 64; o > 0; o >>= 1) { if (t < o) red[t] += red[t + o]; __syncthreads(); }
    float mu = red[0] / 128.f; __syncthreads();
    float d = (t < 128) ? (s - mu) : 0.f;
    if (t < 128) red[t] = d * d;
    __syncthreads();
    for (int o = 64; o > 0; o >>= 1) { if (t < o) red[t] += red[t + o]; __syncthreads(); }
    float var = red[0] / 128.f; __syncthreads();
    if (t < 128) sh[t] = fmaxf(d * rsqrtf(var + 1e-5f) * g1[t] + be1[t], 0.f);
    __syncthreads();

    float s2b = 0.f;
    if (t < 64) {
        s2b = fc2b[t];
        float a0 = 0.f, a1 = 0.f;
        for (int kk = 0; kk < 128; kk += 2) {
            a0 = fmaf(sh[kk], fc2W[kk * 64 + t], a0);
            a1 = fmaf(sh[kk + 1], fc2W[(kk + 1) * 64 + t], a1);
        }
        s2b += a0 + a1;
    }
    __syncthreads();
    if (t < 128) red[t] = (t < 64) ? s2b : 0.f;
    __syncthreads();
    for (int o = 64; o > 0; o >>= 1) { if (t < o) red[t] += red[t + o]; __syncthreads(); }
    float mu2 = red[0] / 64.f; __syncthreads();
    float d2 = (t < 64) ? (s2b - mu2) : 0.f;
    if (t < 128) red[t] = d2 * d2;
    __syncthreads();
    for (int o = 64; o > 0; o >>= 1) { if (t < o) red[t] += red[t + o]; __syncthreads(); }
    float var2 = red[0] / 64.f; __syncthreads();
    if (t < 64) sh[t] = fmaxf(d2 * rsqrtf(var2 + 1e-5f) * g2[t] + be2[t], 0.f);
    __syncthreads();

    if (t == 0) {
        float o = fc3b[0];
        for (int kk = 0; kk < 64; kk++) o = fmaf(sh[kk], fc3W[kk], o);
        out[g] = 1.f / (1.f + expf(-o));
    }
}

// ---------------- launch ----------------
extern "C" void kernel_launch(void* const* d_in, const int* in_sizes, int n_in,
                              void* d_out, int out_size)
{
    const float* x1 = (const float*)d_in[0];
    const int* ei1 = (const int*)d_in[1];
    const float* x2 = (const float*)d_in[3];
    const int* ei2 = (const int*)d_in[4];
    const float* W1a = (const float*)d_in[5];  const float* b1a = (const float*)d_in[6];
    const float* W1b = (const float*)d_in[7];  const float* b1b = (const float*)d_in[8];
    const float* W2a = (const float*)d_in[9];  const float* b2a = (const float*)d_in[10];
    const float* W2b = (const float*)d_in[11]; const float* b2b = (const float*)d_in[12];
    const float* fc1W = (const float*)d_in[13]; const float* fc1b = (const float*)d_in[14];
    const float* g1 = (const float*)d_in[15];   const float* be1 = (const float*)d_in[16];
    const float* fc2W = (const float*)d_in[17]; const float* fc2b = (const float*)d_in[18];
    const float* g2 = (const float*)d_in[19];   const float* be2 = (const float*)d_in[20];
    const float* fc3W = (const float*)d_in[21]; const float* fc3b = (const float*)d_in[22];
    float* out = (float*)d_out;

    int E1 = in_sizes[1] / 2;
    int E2 = in_sizes[4] / 2;

    float *t, *agg, *h, *u, *aggu, *o;
    float *keys, *ckey, *pooled, *refp;
    unsigned *hist, *thr, *cnt;
    int *cidx, *sel;
    unsigned *deg, *off, *cur, *bsum;
    int *csr;
    cudaGetSymbolAddress((void**)&t, g_t);
    cudaGetSymbolAddress((void**)&agg, g_agg);
    cudaGetSymbolAddress((void**)&h, g_h);
    cudaGetSymbolAddress((void**)&u, g_u);
    cudaGetSymbolAddress((void**)&aggu, g_aggu);
    cudaGetSymbolAddress((void**)&o, g_o);
    cudaGetSymbolAddress((void**)&keys, g_keys);
    cudaGetSymbolAddress((void**)&refp, g_ref);
    cudaGetSymbolAddress((void**)&hist, g_hist);
    cudaGetSymbolAddress((void**)&thr, g_thr);
    cudaGetSymbolAddress((void**)&cnt, g_cnt);
    cudaGetSymbolAddress((void**)&cidx, g_cidx);
    cudaGetSymbolAddress((void**)&ckey, g_ckey);
    cudaGetSymbolAddress((void**)&sel, g_sel);
    cudaGetSymbolAddress((void**)&pooled, g_pooled);
    cudaGetSymbolAddress((void**)&deg, g_deg);
    cudaGetSymbolAddress((void**)&off, g_off);
    cudaGetSymbolAddress((void**)&cur, g_cur);
    cudaGetSymbolAddress((void**)&csr, g_csr);
    cudaGetSymbolAddress((void**)&bsum, g_bsum);

    const float* o2p = o + (size_t)N1V * 64;   // graph2 output rows

    int gy = (NT + 127) / 128;                 // 1565
    int nb = (NT + 1023) / 1024;               // 196

    // ===== combined CSR build =====
    zero4_k<<<(NTP / 4 + 255) / 256, 256>>>((float4*)deg, NTP / 4);
    deg_k<<<(E1 + 255) / 256, 256>>>(ei1 + E1, E1, 0, deg);
    deg_k<<<(E2 + 255) / 256, 256>>>(ei2 + E2, E2, N1V, deg);
    scan_block_k<<<nb, 256>>>(deg, off, bsum, NT);
    scan_top_k<<<1, 256>>>(bsum, nb);
    scan_add_k<<<nb, 256>>>(off, cur, bsum, NT);
    fill_k<<<(E1 + 255) / 256, 256>>>(ei1, ei1 + E1, E1, 0, off, cur, csr);
    fill_k<<<(E2 + 255) / 256, 256>>>(ei2, ei2 + E2, E2, N1V, off, cur, csr);

    // ===== combined GIN =====
    gemm_k<false, false><<<dim3(2, gy), 256>>>(x1, x2, N1V, W1a, nullptr, t, NT, 128, 128,
                                               nullptr, nullptr, nullptr);
    agg_k<128><<<(NT * 32 + 255) / 256, 256>>>(t, csr, off, deg, b1a, agg, NT);
    gemm_k<true, false><<<dim3(2, gy), 256>>>(agg, agg, NT + 256, W1b, b1b, h, NT, 128, 128,
                                              nullptr, nullptr, nullptr);

    gemm_k<false, false><<<dim3(1, gy), 256>>>(h, h, NT + 256, W2a, nullptr, u, NT, 128, 64,
                                               nullptr, nullptr, nullptr);
    agg_k<64><<<(NT * 16 + 255) / 256, 256>>>(u, csr, off, deg, b2a, aggu, NT);

    // hist zero + ref row must precede the fused final gemm
    zero4_k<<<(BGR * 65536 / 4 + 255) / 256, 256>>>((float4*)hist, BGR * 65536 / 4);
    ref_k<<<1, 64>>>(aggu, W2b, b2b, refp);
    gemm_k<true, true><<<dim3(1, gy), 256>>>(aggu, aggu, NT + 256, W2b, b2b, o, NT, 64, 64,
                                             refp, keys, hist);

    // ===== selection =====
    thresh_k<<<BGR, 256>>>(hist, thr, cnt);
    collect_k<<<(N1V + 255) / 256, 256>>>(keys, thr, cnt, cidx, ckey);
    select_k<<<BGR, 256>>>(cnt, cidx, ckey, sel);

    // ===== pooled distances + head =====
    pool_k<<<BGR * KSEL, 256>>>(o, o2p, sel, pooled);
    head_k<<<BGR, 256>>>(pooled, fc1W, fc1b, g1, be1, fc2W, fc2b, g2, be2, fc3W, fc3b, out);
}

// round 14
// speedup vs baseline: 1.4769x; 1.1101x over previous
#include <cuda_runtime.h>
#include <math.h>

#define N1V 200000
#define BGR 8
#define NPG 25000
#define NN2 199
#define NT  (N1V + NN2)          // combined node count
#define NTP (N1V + 256)          // padded scratch rows
#define KSEL 50
#define E1MAX 2000000
#define E2MAX 4096
#define NBUCK 16384              // 14-bit histogram (float bits >> 18)

// ---------------- scratch (combined graphs) ----------------
__device__ __align__(16) float g_t[(size_t)NTP * 128];
__device__ __align__(16) float g_agg[(size_t)NTP * 128];
__device__ __align__(16) float g_h[(size_t)NTP * 128];
__device__ __align__(16) float g_u[(size_t)NTP * 64];
__device__ __align__(16) float g_aggu[(size_t)NTP * 64];
__device__ __align__(16) float g_o[(size_t)NTP * 64];

__device__ __align__(16) unsigned g_deg[NTP];
__device__ __align__(16) unsigned g_off[NTP];
__device__ __align__(16) unsigned g_cur[NTP];
__device__ __align__(16) int      g_csr[E1MAX + E2MAX];
__device__ __align__(16) unsigned g_bsum[256];

__device__ __align__(16) float    g_keys[N1V];
__device__ __align__(16) float    g_ref[64];
__device__ __align__(16) unsigned g_hist[BGR * NBUCK];
__device__ __align__(16) unsigned g_thr[BGR];
__device__ __align__(16) unsigned g_cnt[BGR];
__device__ __align__(16) int      g_cidx[BGR * NPG];
__device__ __align__(16) float    g_ckey[BGR * NPG];
__device__ __align__(16) int      g_sel[BGR * KSEL];
__device__ __align__(16) float    g_pooled[BGR * KSEL * NN2];

// packed f32x2 FMA (exact fp32 per lane)
__device__ __forceinline__ void ffma2(unsigned long long& d, unsigned long long a, unsigned long long b) {
    asm("fma.rn.f32x2 %0, %1, %2, %3;" : "=l"(d) : "l"(a), "l"(b), "l"(d));
}
__device__ __forceinline__ unsigned long long dup_f32x2(float b) {
    unsigned long long r;
    asm("mov.b64 %0, {%1, %1};" : "=l"(r) : "f"(b));
    return r;
}

// ---------------- zero ----------------
__global__ void zero4_k(float4* p, int n4) {
    int i = blockIdx.x * blockDim.x + threadIdx.x;
    if (i < n4) p[i] = make_float4(0.f, 0.f, 0.f, 0.f);
}

// ---------------- CSR build (combined) ----------------
__global__ void deg_k(const int* __restrict__ dst, int E, int off,
                      unsigned* __restrict__ deg) {
    int e = blockIdx.x * blockDim.x + threadIdx.x;
    if (e < E) atomicAdd(&deg[dst[e] + off], 1u);
}

__global__ void scan_block_k(const unsigned* __restrict__ in, unsigned* __restrict__ out,
                             unsigned* __restrict__ blocksum, int N) {
    __shared__ unsigned warp_tot[8];
    int t = threadIdx.x;
    int base = blockIdx.x * 1024 + t * 4;
    unsigned v0 = (base + 0 < N) ? in[base + 0] : 0u;
    unsigned v1 = (base + 1 < N) ? in[base + 1] : 0u;
    unsigned v2 = (base + 2 < N) ? in[base + 2] : 0u;
    unsigned v3 = (base + 3 < N) ? in[base + 3] : 0u;
    unsigned s = v0 + v1 + v2 + v3;
    unsigned x = s;
#pragma unroll
    for (int o = 1; o < 32; o <<= 1) {
        unsigned y = __shfl_up_sync(0xffffffffu, x, o);
        if ((t & 31) >= o) x += y;
    }
    if ((t & 31) == 31) warp_tot[t >> 5] = x;
    __syncthreads();
    if (t < 32) {
        unsigned w = (t < 8) ? warp_tot[t] : 0u;
        unsigned wx = w;
#pragma unroll
        for (int o = 1; o < 8; o <<= 1) {
            unsigned y = __shfl_up_sync(0xffffffffu, wx, o);
            if (t >= o) wx += y;
        }
        if (t == 7) blocksum[blockIdx.x] = wx;
        if (t < 8) warp_tot[t] = wx - w;
    }
    __syncthreads();
    unsigned run = warp_tot[t >> 5] + (x - s);
    if (base + 0 < N) out[base + 0] = run; run += v0;
    if (base + 1 < N) out[base + 1] = run; run += v1;
    if (base + 2 < N) out[base + 2] = run; run += v2;
    if (base + 3 < N) out[base + 3] = run;
}

__global__ void scan_top_k(unsigned* bs, int nb) {
    __shared__ unsigned wsum[8];
    int t = threadIdx.x;
    int lane = t & 31, w = t >> 5;
    unsigned v = (t < nb) ? bs[t] : 0u;
    unsigned x = v;
#pragma unroll
    for (int o = 1; o < 32; o <<= 1) {
        unsigned y = __shfl_up_sync(0xffffffffu, x, o);
        if (lane >= o) x += y;
    }
    if (lane == 31) wsum[w] = x;
    __syncthreads();
    if (t == 0) {
        unsigned run = 0;
#pragma unroll
        for (int i = 0; i < 8; i++) { unsigned tmp = wsum[i]; wsum[i] = run; run += tmp; }
    }
    __syncthreads();
    if (t < nb) bs[t] = wsum[w] + x - v;
}

// adds block prefix AND zeroes the fill-cursor array
__global__ void scan_add_k(unsigned* out, unsigned* cur, const unsigned* __restrict__ bs, int N) {
    int i = blockIdx.x * 1024 + threadIdx.x * 4;
    unsigned b = bs[blockIdx.x];
#pragma unroll
    for (int j = 0; j < 4; j++)
        if (i + j < N) { out[i + j] += b; cur[i + j] = 0u; }
}

__global__ void fill_k(const int* __restrict__ src, const int* __restrict__ dst, int E, int off,
                       const unsigned* __restrict__ offs, unsigned* __restrict__ cur,
                       int* __restrict__ csr) {
    int e = blockIdx.x * blockDim.x + threadIdx.x;
    if (e < E) {
        int d = dst[e] + off;
        unsigned p = offs[d] + atomicAdd(&cur[d], 1u);
        csr[p] = src[e] + off;
    }
}

// ---------------- gather aggregation with fused GIN epilogue ----------------
// D=64 full-row version (layer 2)
template<int D>
__global__ __launch_bounds__(256)
void agg_k(const float* __restrict__ V, const int* __restrict__ csr,
           const unsigned* __restrict__ off, const unsigned* __restrict__ deg,
           const float* __restrict__ bias, float* __restrict__ O, int N) {
    const int G = D / 4;
    int tid = blockIdx.x * blockDim.x + threadIdx.x;
    int node = tid / G;
    int lane = tid % G;
    if (node >= N) return;
    unsigned s0 = off[node], dn = deg[node];
    float4 accA = make_float4(0.f, 0.f, 0.f, 0.f);
    float4 accB = make_float4(0.f, 0.f, 0.f, 0.f);
    unsigned j = 0;
    for (; j + 4 <= dn; j += 4) {
        int i0 = csr[s0 + j + 0], i1 = csr[s0 + j + 1];
        int i2 = csr[s0 + j + 2], i3 = csr[s0 + j + 3];
        float4 a0 = *(const float4*)(V + (size_t)i0 * D + lane * 4);
        float4 a1 = *(const float4*)(V + (size_t)i1 * D + lane * 4);
        float4 a2 = *(const float4*)(V + (size_t)i2 * D + lane * 4);
        float4 a3 = *(const float4*)(V + (size_t)i3 * D + lane * 4);
        accA.x += a0.x + a1.x; accA.y += a0.y + a1.y;
        accA.z += a0.z + a1.z; accA.w += a0.w + a1.w;
        accB.x += a2.x + a3.x; accB.y += a2.y + a3.y;
        accB.z += a2.z + a3.z; accB.w += a2.w + a3.w;
    }
    for (; j < dn; j++) {
        int i0 = csr[s0 + j];
        float4 a0 = *(const float4*)(V + (size_t)i0 * D + lane * 4);
        accA.x += a0.x; accA.y += a0.y; accA.z += a0.z; accA.w += a0.w;
    }
    float4 self = *(const float4*)(V + (size_t)node * D + lane * 4);
    float4 b = *(const float4*)(bias + lane * 4);
    float4 o;
    o.x = fmaxf(accA.x + accB.x + self.x + b.x, 0.f);
    o.y = fmaxf(accA.y + accB.y + self.y + b.y, 0.f);
    o.z = fmaxf(accA.z + accB.z + self.z + b.z, 0.f);
    o.w = fmaxf(accA.w + accB.w + self.w + b.w, 0.f);
    *(float4*)(O + (size_t)node * D + lane * 4) = o;
}

// column-half version for D=128 rows (layer 1): each pass covers 64 columns
// starting at colOff; gather footprint per pass = 51 MB (L2-resident).
__global__ __launch_bounds__(256)
void agg_half_k(const float* __restrict__ V, const int* __restrict__ csr,
                const unsigned* __restrict__ off, const unsigned* __restrict__ deg,
                const float* __restrict__ bias, float* __restrict__ O, int N,
                int colOff) {
    const int G = 16;                      // 16 lanes x 4 floats = 64 cols
    int tid = blockIdx.x * blockDim.x + threadIdx.x;
    int node = tid / G;
    int lane = tid % G;
    if (node >= N) return;
    int cb = colOff + lane * 4;
    unsigned s0 = off[node], dn = deg[node];
    float4 accA = make_float4(0.f, 0.f, 0.f, 0.f);
    float4 accB = make_float4(0.f, 0.f, 0.f, 0.f);
    unsigned j = 0;
    for (; j + 4 <= dn; j += 4) {
        int i0 = csr[s0 + j + 0], i1 = csr[s0 + j + 1];
        int i2 = csr[s0 + j + 2], i3 = csr[s0 + j + 3];
        float4 a0 = *(const float4*)(V + (size_t)i0 * 128 + cb);
        float4 a1 = *(const float4*)(V + (size_t)i1 * 128 + cb);
        float4 a2 = *(const float4*)(V + (size_t)i2 * 128 + cb);
        float4 a3 = *(const float4*)(V + (size_t)i3 * 128 + cb);
        accA.x += a0.x + a1.x; accA.y += a0.y + a1.y;
        accA.z += a0.z + a1.z; accA.w += a0.w + a1.w;
        accB.x += a2.x + a3.x; accB.y += a2.y + a3.y;
        accB.z += a2.z + a3.z; accB.w += a2.w + a3.w;
    }
    for (; j < dn; j++) {
        int i0 = csr[s0 + j];
        float4 a0 = *(const float4*)(V + (size_t)i0 * 128 + cb);
        accA.x += a0.x; accA.y += a0.y; accA.z += a0.z; accA.w += a0.w;
    }
    float4 self = *(const float4*)(V + (size_t)node * 128 + cb);
    float4 b = *(const float4*)(bias + cb);
    float4 o;
    o.x = fmaxf(accA.x + accB.x + self.x + b.x, 0.f);
    o.y = fmaxf(accA.y + accB.y + self.y + b.y, 0.f);
    o.z = fmaxf(accA.z + accB.z + self.z + b.z, 0.f);
    o.w = fmaxf(accA.w + accB.w + self.w + b.w, 0.f);
    *(float4*)(O + (size_t)node * 128 + cb) = o;
}

// ---------------- reference row for keys: ref = relu(aggu[N1V+198] @ W2b + b2b) ----------------
__global__ void ref_k(const float* __restrict__ aggu, const float* __restrict__ W2b,
                      const float* __restrict__ b2b, float* __restrict__ ref) {
    int c = threadIdx.x;  // 64
    const float* a = aggu + (size_t)(N1V + 198) * 64;
    float s = b2b[c];
    for (int k = 0; k < 64; k++) s = fmaf(a[k], W2b[k * 64 + c], s);
    ref[c] = fmaxf(s, 0.f);
}

// ---------------- SGEMM (FFMA2, frozen): C = A @ W (+bout)(+relu) ----------------
// KEYS: fused per-row squared-distance-to-ref + histogram (final gemm only).
template<bool RELU_OUT, bool KEYS>
__global__ __launch_bounds__(256)
void gemm_k(const float* __restrict__ A1, const float* __restrict__ A2, int N1,
            const float* __restrict__ W, const float* __restrict__ bout,
            float* __restrict__ C, int N, int K, int Co,
            const float* __restrict__ refp, float* __restrict__ keys,
            unsigned* __restrict__ hist)
{
    const int BM = 128, BN = 64, BK = 16;
    __shared__ float As[BK][BM + 4];
    __shared__ float Bs[BK][BN + 4];

    int tid = threadIdx.x;
    int rowBase = blockIdx.y * BM;
    int colBase = blockIdx.x * BN;
    int tx = tid & 15;
    int ty = tid >> 4;

    unsigned long long acc2[4][4];
#pragma unroll
    for (int p = 0; p < 4; p++)
#pragma unroll
        for (int j = 0; j < 4; j++) acc2[p][j] = 0ull;

    for (int k0 = 0; k0 < K; k0 += BK) {
        {
            int row = tid >> 1;
            int kk = (tid & 1) * 8;
            int r = rowBase + row;
            if (r < N) {
                const float* pA = (r < N1) ? (A1 + (size_t)r * K)
                                           : (A2 + (size_t)(r - N1) * K);
                pA += k0 + kk;
                float4 v0 = *(const float4*)(pA);
                float4 v1 = *(const float4*)(pA + 4);
                As[kk + 0][row] = v0.x; As[kk + 1][row] = v0.y;
                As[kk + 2][row] = v0.z; As[kk + 3][row] = v0.w;
                As[kk + 4][row] = v1.x; As[kk + 5][row] = v1.y;
                As[kk + 6][row] = v1.z; As[kk + 7][row] = v1.w;
            } else {
#pragma unroll
                for (int i = 0; i < 8; i++) As[kk + i][row] = 0.f;
            }
        }
        {
            int k = tid >> 4;
            int c = (tid & 15) * 4;
            float4 v = *(const float4*)(W + (size_t)(k0 + k) * Co + colBase + c);
            Bs[k][c + 0] = v.x; Bs[k][c + 1] = v.y;
            Bs[k][c + 2] = v.z; Bs[k][c + 3] = v.w;
        }
        __syncthreads();

#pragma unroll
        for (int k = 0; k < BK; k++) {
            const unsigned long long* a2p =
                (const unsigned long long*)&As[k][ty * 8];
            unsigned long long a2[4];
#pragma unroll
            for (int p = 0; p < 4; p++) a2[p] = a2p[p];
            unsigned long long bb[4];
#pragma unroll
            for (int j = 0; j < 4; j++) bb[j] = dup_f32x2(Bs[k][tx * 4 + j]);
#pragma unroll
            for (int p = 0; p < 4; p++)
#pragma unroll
                for (int j = 0; j < 4; j++) ffma2(acc2[p][j], a2[p], bb[j]);
        }
        __syncthreads();
    }

    float rf[4];
    if (KEYS) {
#pragma unroll
        for (int j = 0; j < 4; j++) rf[j] = refp[tx * 4 + j];
    }

#pragma unroll
    for (int p = 0; p < 4; p++) {
#pragma unroll
        for (int half = 0; half < 2; half++) {
            int r = rowBase + ty * 8 + 2 * p + half;
            float4 v;
            float tmp[4];
#pragma unroll
            for (int j = 0; j < 4; j++) {
                float lo, hi;
                asm("mov.b64 {%0, %1}, %2;" : "=f"(lo), "=f"(hi) : "l"(acc2[p][j]));
                tmp[j] = half ? hi : lo;
            }
            v.x = tmp[0]; v.y = tmp[1]; v.z = tmp[2]; v.w = tmp[3];
            int c = colBase + tx * 4;
            if (bout) {
                v.x += bout[c + 0]; v.y += bout[c + 1];
                v.z += bout[c + 2]; v.w += bout[c + 3];
            }
            if (RELU_OUT) {
                v.x = fmaxf(v.x, 0.f); v.y = fmaxf(v.y, 0.f);
                v.z = fmaxf(v.z, 0.f); v.w = fmaxf(v.w, 0.f);
            }
            if (r < N)
                *(float4*)(C + (size_t)r * Co + c) = v;

            if (KEYS) {
                float d0 = v.x - rf[0], d1 = v.y - rf[1];
                float d2 = v.z - rf[2], d3 = v.w - rf[3];
                float kp = d0 * d0 + d1 * d1 + d2 * d2 + d3 * d3;
                kp += __shfl_xor_sync(0xffffffffu, kp, 1);
                kp += __shfl_xor_sync(0xffffffffu, kp, 2);
                kp += __shfl_xor_sync(0xffffffffu, kp, 4);
                kp += __shfl_xor_sync(0xffffffffu, kp, 8);
                if (tx == 0 && r < N1V) {
                    keys[r] = kp;
                    unsigned b = __float_as_uint(kp) >> 18;
                    atomicAdd(&hist[(r / NPG) * NBUCK + b], 1u);
                }
            }
        }
    }
}

// also zeroes cnt[g]; NBUCK=16384 buckets, 64 per thread
__global__ void thresh_k(const unsigned* __restrict__ hist, unsigned* __restrict__ thr,
                         unsigned* __restrict__ cnt)
{
    int g = blockIdx.x;
    int t = threadIdx.x;
    __shared__ unsigned csum[256];
    const unsigned* h = hist + g * NBUCK;
    unsigned s = 0;
    for (int b = 0; b < 64; b++) s += h[t * 64 + b];
    csum[t] = s;
    __syncthreads();
    if (t == 0) {
        cnt[g] = 0u;
        unsigned cum = 0;
        int chunk = 255;
        for (; chunk >= 0; chunk--) {
            if (cum + csum[chunk] >= KSEL) break;
            cum += csum[chunk];
        }
        unsigned c2 = cum;
        int b = chunk * 64 + 63;
        for (; b >= chunk * 64; b--) {
            c2 += h[b];
            if (c2 >= KSEL) break;
        }
        thr[g] = (unsigned)b;
    }
}

__global__ void collect_k(const float* __restrict__ keys, const unsigned* __restrict__ thr,
                          unsigned* __restrict__ cnt, int* __restrict__ cidx,
                          float* __restrict__ ckey)
{
    int i = blockIdx.x * blockDim.x + threadIdx.x;
    if (i >= N1V) return;
    int g = i / NPG;
    float k = keys[i];
    if ((__float_as_uint(k) >> 18) >= thr[g]) {
        unsigned p = atomicAdd(&cnt[g], 1u);
        cidx[g * NPG + p] = i;
        ckey[g * NPG + p] = k;
    }
}

__global__ void select_k(const unsigned* __restrict__ cnt, const int* __restrict__ cidx,
                         const float* __restrict__ ckey, int* __restrict__ sel)
{
    int g = blockIdx.x;
    int M = (int)cnt[g];
    const int* idx = cidx + g * NPG;
    const float* key = ckey + g * NPG;
    for (int c = threadIdx.x; c < M; c += blockDim.x) {
        float kc = key[c];
        int ic = idx[c];
        int rank = 0;
        for (int j = 0; j < M; j++) {
            float kj = key[j];
            if (kj > kc || (kj == kc && idx[j] < ic)) rank++;
        }
        if (rank < KSEL) sel[g * KSEL + rank] = ic;
    }
}

__global__ void pool_k(const float* __restrict__ o1, const float* __restrict__ o2,
                       const int* __restrict__ sel, float* __restrict__ pooled)
{
    __shared__ float a[64];
    int gr = blockIdx.x;
    int node = sel[gr];
    int t = threadIdx.x;
    if (t < 64) a[t] = o1[(size_t)node * 64 + t];
    __syncthreads();
    if (t < NN2) {
        const float* b = o2 + t * 64;
        float s = 0.f;
#pragma unroll
        for (int c = 0; c < 64; c++) {
            float d = a[c] - b[c];
            s += d * d;
        }
        pooled[gr * NN2 + t] = sqrtf(s);
    }
}

// head: 256 threads. fc1 split 2-way over k with 4 independent partials.
__global__ void head_k(const float* __restrict__ pooled,
                       const float* __restrict__ fc1W, const float* __restrict__ fc1b,
                       const float* __restrict__ g1, const float* __restrict__ be1,
                       const float* __restrict__ fc2W, const float* __restrict__ fc2b,
                       const float* __restrict__ g2, const float* __restrict__ be2,
                       const float* __restrict__ fc3W, const float* __restrict__ fc3b,
                       float* __restrict__ out)
{
    int g = blockIdx.x;
    int t = threadIdx.x;          // 256
    int col = t & 127;
    int half = t >> 7;
    __shared__ float part[256];
    __shared__ float sh[128];
    __shared__ float red[128];
    const float* p = pooled + g * (KSEL * NN2);

    const int KT = KSEL * NN2;            // 9950
    const int KH = KT / 2;                // 4975
    int k0 = half * KH, k1 = k0 + KH;
    float s0 = 0.f, s1 = 0.f, s2 = 0.f, s3 = 0.f;
    int k = k0;
    for (; k + 4 <= k1; k += 4) {
        s0 = fmaf(p[k + 0], fc1W[(size_t)(k + 0) * 128 + col], s0);
        s1 = fmaf(p[k + 1], fc1W[(size_t)(k + 1) * 128 + col], s1);
        s2 = fmaf(p[k + 2], fc1W[(size_t)(k + 2) * 128 + col], s2);
        s3 = fmaf(p[k + 3], fc1W[(size_t)(k + 3) * 128 + col], s3);
    }
    for (; k < k1; k++) s0 = fmaf(p[k], fc1W[(size_t)k * 128 + col], s0);
    part[t] = ((s0 + s1) + (s2 + s3));
    __syncthreads();

    float s = 0.f;
    if (t < 128) s = part[t] + part[t + 128] + fc1b[t];

    if (t < 128) red[t] = s;
    __syncthreads();
    for (int o = 64; o > 0; o >>= 1) { if (t < o) red[t] += red[t + o]; __syncthreads(); }
    float mu = red[0] / 128.f; __syncthreads();
    float d = (t < 128) ? (s - mu) : 0.f;
    if (t < 128) red[t] = d * d;
    __syncthreads();
    for (int o = 64; o > 0; o >>= 1) { if (t < o) red[t] += red[t + o]; __syncthreads(); }
    float var = red[0] / 128.f; __syncthreads();
    if (t < 128) sh[t] = fmaxf(d * rsqrtf(var + 1e-5f) * g1[t] + be1[t], 0.f);
    __syncthreads();

    float s2b = 0.f;
    if (t < 64) {
        s2b = fc2b[t];
        float a0 = 0.f, a1 = 0.f;
        for (int kk = 0; kk < 128; kk += 2) {
            a0 = fmaf(sh[kk], fc2W[kk * 64 + t], a0);
            a1 = fmaf(sh[kk + 1], fc2W[(kk + 1) * 64 + t], a1);
        }
        s2b += a0 + a1;
    }
    __syncthreads();
    if (t < 128) red[t] = (t < 64) ? s2b : 0.f;
    __syncthreads();
    for (int o = 64; o > 0; o >>= 1) { if (t < o) red[t] += red[t + o]; __syncthreads(); }
    float mu2 = red[0] / 64.f; __syncthreads();
    float d2 = (t < 64) ? (s2b - mu2) : 0.f;
    if (t < 128) red[t] = d2 * d2;
    __syncthreads();
    for (int o = 64; o > 0; o >>= 1) { if (t < o) red[t] += red[t + o]; __syncthreads(); }
    float var2 = red[0] / 64.f; __syncthreads();
    if (t < 64) sh[t] = fmaxf(d2 * rsqrtf(var2 + 1e-5f) * g2[t] + be2[t], 0.f);
    __syncthreads();

    if (t == 0) {
        float o = fc3b[0];
        for (int kk = 0; kk < 64; kk++) o = fmaf(sh[kk], fc3W[kk], o);
        out[g] = 1.f / (1.f + expf(-o));
    }
}

// ---------------- launch ----------------
extern "C" void kernel_launch(void* const* d_in, const int* in_sizes, int n_in,
                              void* d_out, int out_size)
{
    const float* x1 = (const float*)d_in[0];
    const int* ei1 = (const int*)d_in[1];
    const float* x2 = (const float*)d_in[3];
    const int* ei2 = (const int*)d_in[4];
    const float* W1a = (const float*)d_in[5];  const float* b1a = (const float*)d_in[6];
    const float* W1b = (const float*)d_in[7];  const float* b1b = (const float*)d_in[8];
    const float* W2a = (const float*)d_in[9];  const float* b2a = (const float*)d_in[10];
    const float* W2b = (const float*)d_in[11]; const float* b2b = (const float*)d_in[12];
    const float* fc1W = (const float*)d_in[13]; const float* fc1b = (const float*)d_in[14];
    const float* g1 = (const float*)d_in[15];   const float* be1 = (const float*)d_in[16];
    const float* fc2W = (const float*)d_in[17]; const float* fc2b = (const float*)d_in[18];
    const float* g2 = (const float*)d_in[19];   const float* be2 = (const float*)d_in[20];
    const float* fc3W = (const float*)d_in[21]; const float* fc3b = (const float*)d_in[22];
    float* out = (float*)d_out;

    int E1 = in_sizes[1] / 2;
    int E2 = in_sizes[4] / 2;

    float *t, *agg, *h, *u, *aggu, *o;
    float *keys, *ckey, *pooled, *refp;
    unsigned *hist, *thr, *cnt;
    int *cidx, *sel;
    unsigned *deg, *off, *cur, *bsum;
    int *csr;
    cudaGetSymbolAddress((void**)&t, g_t);
    cudaGetSymbolAddress((void**)&agg, g_agg);
    cudaGetSymbolAddress((void**)&h, g_h);
    cudaGetSymbolAddress((void**)&u, g_u);
    cudaGetSymbolAddress((void**)&aggu, g_aggu);
    cudaGetSymbolAddress((void**)&o, g_o);
    cudaGetSymbolAddress((void**)&keys, g_keys);
    cudaGetSymbolAddress((void**)&refp, g_ref);
    cudaGetSymbolAddress((void**)&hist, g_hist);
    cudaGetSymbolAddress((void**)&thr, g_thr);
    cudaGetSymbolAddress((void**)&cnt, g_cnt);
    cudaGetSymbolAddress((void**)&cidx, g_cidx);
    cudaGetSymbolAddress((void**)&ckey, g_ckey);
    cudaGetSymbolAddress((void**)&sel, g_sel);
    cudaGetSymbolAddress((void**)&pooled, g_pooled);
    cudaGetSymbolAddress((void**)&deg, g_deg);
    cudaGetSymbolAddress((void**)&off, g_off);
    cudaGetSymbolAddress((void**)&cur, g_cur);
    cudaGetSymbolAddress((void**)&csr, g_csr);
    cudaGetSymbolAddress((void**)&bsum, g_bsum);

    const float* o2p = o + (size_t)N1V * 64;   // graph2 output rows

    int gy = (NT + 127) / 128;                 // 1565
    int nb = (NT + 1023) / 1024;               // 196

    // ===== combined CSR build =====
    zero4_k<<<(NTP / 4 + 255) / 256, 256>>>((float4*)deg, NTP / 4);
    deg_k<<<(E1 + 255) / 256, 256>>>(ei1 + E1, E1, 0, deg);
    deg_k<<<(E2 + 255) / 256, 256>>>(ei2 + E2, E2, N1V, deg);
    scan_block_k<<<nb, 256>>>(deg, off, bsum, NT);
    scan_top_k<<<1, 256>>>(bsum, nb);
    scan_add_k<<<nb, 256>>>(off, cur, bsum, NT);
    fill_k<<<(E1 + 255) / 256, 256>>>(ei1, ei1 + E1, E1, 0, off, cur, csr);
    fill_k<<<(E2 + 255) / 256, 256>>>(ei2, ei2 + E2, E2, N1V, off, cur, csr);

    // ===== combined GIN =====
    gemm_k<false, false><<<dim3(2, gy), 256>>>(x1, x2, N1V, W1a, nullptr, t, NT, 128, 128,
                                               nullptr, nullptr, nullptr);
    // layer-1 aggregation in two 64-col passes (L2-resident gather footprint)
    agg_half_k<<<(NT * 16 + 255) / 256, 256>>>(t, csr, off, deg, b1a, agg, NT, 0);
    agg_half_k<<<(NT * 16 + 255) / 256, 256>>>(t, csr, off, deg, b1a, agg, NT, 64);
    gemm_k<true, false><<<dim3(2, gy), 256>>>(agg, agg, NT + 256, W1b, b1b, h, NT, 128, 128,
                                              nullptr, nullptr, nullptr);

    gemm_k<false, false><<<dim3(1, gy), 256>>>(h, h, NT + 256, W2a, nullptr, u, NT, 128, 64,
                                               nullptr, nullptr, nullptr);
    agg_k<64><<<(NT * 16 + 255) / 256, 256>>>(u, csr, off, deg, b2a, aggu, NT);

    // hist zero + ref row must precede the fused final gemm
    zero4_k<<<(BGR * NBUCK / 4 + 255) / 256, 256>>>((float4*)hist, BGR * NBUCK / 4);
    ref_k<<<1, 64>>>(aggu, W2b, b2b, refp);
    gemm_k<true, true><<<dim3(1, gy), 256>>>(aggu, aggu, NT + 256, W2b, b2b, o, NT, 64, 64,
                                             refp, keys, hist);

    // ===== selection =====
    thresh_k<<<BGR, 256>>>(hist, thr, cnt);
    collect_k<<<(N1V + 255) / 256, 256>>>(keys, thr, cnt, cidx, ckey);
    select_k<<<BGR, 256>>>(cnt, cidx, ckey, sel);

    // ===== pooled distances + head =====
    pool_k<<<BGR * KSEL, 256>>>(o, o2p, sel, pooled);
    head_k<<<BGR, 256>>>(pooled, fc1W, fc1b, g1, be1, fc2W, fc2b, g2, be2, fc3W, fc3b, out);
}